// round 9
// baseline (speedup 1.0000x reference)
#include <cuda_runtime.h>

// Problem constants
#define Bn     1024
#define Kc     1056
#define Nc     2112
#define Mc     1056
#define DVc    5
#define NSYMc  528
#define NITERc 20

#define Tthr   528           // threads per block (HW max is 1024; 1056 was illegal)
#define CPT    2             // check-rows per thread: Mc / Tthr == 2

#define EXCLAMP 0.99999994f  // ~ fp32 rounding of exp(-1e-7): reference saturation

__global__ void __launch_bounds__(Tthr, 2)
simplelink_kernel(const int* __restrict__ bits,
                  const int* __restrict__ a_idx,
                  const float* __restrict__ points_re,
                  const float* __restrict__ points_im,
                  const float* __restrict__ noise_re,
                  const float* __restrict__ noise_im,
                  const float* __restrict__ ebno,
                  float* __restrict__ out)
{
    __shared__ float llr_s[Nc];
    __shared__ float totA[Kc];   // info-var marginals (llr + sum c2v), double-buffered
    __shared__ float totB[Kc];
    __shared__ int   cw_s[Nc];
    __shared__ float pre_s[16], pim_s[16];

    const int b   = blockIdx.x;
    const int tid = threadIdx.x;

    if (tid < 16) { pre_s[tid] = points_re[tid]; pim_s[tid] = points_im[tid]; }

    // ---- load info bits (2 per thread) ----
    cw_s[tid]        = bits[b * Kc + tid];
    cw_s[tid + Tthr] = bits[b * Kc + tid + Tthr];
    __syncthreads();

    // ---- LDPC encode: 2 parities per thread ----
    #pragma unroll
    for (int c = 0; c < CPT; c++) {
        int m = tid + c * Tthr;
        const int* row = a_idx + m * DVc;
        int p = 0;
        #pragma unroll
        for (int j = 0; j < DVc; j++) p += cw_s[row[j]];
        cw_s[Kc + m] = p & 1;
    }
    __syncthreads();

    // ---- noise scaling ----
    const float eb    = ebno[0];
    const float no    = __fdiv_rn(1.0f,
                         __fmul_rn(__fmul_rn(powf(10.0f, __fdiv_rn(eb, 10.0f)), 0.5f), 4.0f));
    const float sigma = sqrtf(__fdiv_rn(no, 2.0f));
    const float inv_no = __fdiv_rn(1.0f, no);

    // ---- QAM map + AWGN + APP demap -> llr (exactly one symbol per thread) ----
    {
        const int s = tid;
        int sym = (cw_s[4*s] << 3) | (cw_s[4*s+1] << 2) | (cw_s[4*s+2] << 1) | cw_s[4*s+3];
        float yre = pre_s[sym] + sigma * noise_re[b * NSYMc + s];
        float yim = pim_s[sym] + sigma * noise_im[b * NSYMc + s];
        float lg[16];
        #pragma unroll
        for (int i = 0; i < 16; i++) {
            float dr = yre - pre_s[i];
            float di = yim - pim_s[i];
            lg[i] = -(dr * dr + di * di) * inv_no;
        }
        #pragma unroll
        for (int j = 0; j < 4; j++) {
            int sh = 3 - j;
            float m0 = -1e30f, m1 = -1e30f;
            #pragma unroll
            for (int i = 0; i < 16; i++) {
                if ((i >> sh) & 1) m1 = fmaxf(m1, lg[i]);
                else               m0 = fmaxf(m0, lg[i]);
            }
            float s0 = 0.0f, s1 = 0.0f;
            #pragma unroll
            for (int i = 0; i < 16; i++) {
                float e = __expf(lg[i] - (((i >> sh) & 1) ? m1 : m0));
                if ((i >> sh) & 1) s1 += e;
                else               s0 += e;
            }
            llr_s[4*s + j] = (__logf(s0) + m0) - (__logf(s1) + m1);
        }
    }
    __syncthreads();

    // ---- BP setup: 2 check-rows per thread ----
    int   idx[CPT][DVc];
    float c2v[CPT][DVc];
    float pn5[CPT], pd5[CPT];
    int   psgn[CPT];
    float llr_r[CPT];

    #pragma unroll
    for (int c = 0; c < CPT; c++) {
        int m = tid + c * Tthr;
        const int* row = a_idx + m * DVc;
        #pragma unroll
        for (int j = 0; j < DVc; j++) { idx[c][j] = row[j]; c2v[c][j] = 0.0f; }
        // parity edge: degree-1 variable, v2c = llr_parity forever
        float lp  = llr_s[Kc + m];
        float avp = fminf(fmaxf(fabsf(lp), 1e-6f), 20.0f);
        float ep  = __expf(-avp);
        pn5[c] = 1.0f - ep;
        pd5[c] = 1.0f + ep;
        psgn[c] = (lp < 0.0f) ? 1 : 0;
        llr_r[c] = llr_s[m];          // info-var llr for slots tid, tid+Tthr
    }

    totA[tid]        = llr_r[0];
    totA[tid + Tthr] = llr_r[1];
    __syncthreads();

    float* cur = totA;
    float* nxt = totB;

    for (int it = 0; it <= NITERc; it++) {
        // scatter c2v into cur (pre-initialized with llr); prep nxt
        #pragma unroll
        for (int c = 0; c < CPT; c++) {
            #pragma unroll
            for (int j = 0; j < DVc; j++) atomicAdd(&cur[idx[c][j]], c2v[c][j]);
        }
        if (it < NITERc) {
            nxt[tid]        = llr_r[0];
            nxt[tid + Tthr] = llr_r[1];
        }
        __syncthreads();
        if (it == NITERc) break;

        // check-node update
        #pragma unroll
        for (int c = 0; c < CPT; c++) {
            float n[DVc], dd[DVc];
            int signs = psgn[c] << DVc;
            #pragma unroll
            for (int j = 0; j < DVc; j++) {
                float v2c = cur[idx[c][j]] - c2v[c][j];
                signs |= ((v2c < 0.0f) ? 1 : 0) << j;
                float av = fminf(fmaxf(fabsf(v2c), 1e-6f), 20.0f);
                float e  = __expf(-av);
                n[j]  = 1.0f - e;
                dd[j] = 1.0f + e;
            }
            int totpar = __popc(signs);
            float sN[DVc], sD[DVc];
            float suN = pn5[c], suD = pd5[c];
            #pragma unroll
            for (int j = DVc - 1; j >= 0; j--) {
                sN[j] = suN; sD[j] = suD;
                suN *= n[j]; suD *= dd[j];
            }
            float prN = 1.0f, prD = 1.0f;
            #pragma unroll
            for (int j = 0; j < DVc; j++) {
                float Pn = prN * sN[j];
                float Pd = prD * sD[j];
                Pn = fminf(Pn, EXCLAMP * Pd);
                float dv = __logf(__fdividef(Pd + Pn, Pd - Pn));  // 2*atanh(Pn/Pd)
                int par = (totpar - ((signs >> j) & 1)) & 1;
                c2v[c][j] = par ? -dv : dv;
                prN *= n[j]; prD *= dd[j];
            }
        }
        __syncthreads();

        float* tmp = cur; cur = nxt; nxt = tmp;
    }

    // ---- outputs: [bits, bits_rx] each [B,K] float ----
    out[b * Kc + tid]                  = (float)cw_s[tid];
    out[b * Kc + tid + Tthr]           = (float)cw_s[tid + Tthr];
    out[Bn * Kc + b * Kc + tid]        = (cur[tid] < 0.0f) ? 1.0f : 0.0f;
    out[Bn * Kc + b * Kc + tid + Tthr] = (cur[tid + Tthr] < 0.0f) ? 1.0f : 0.0f;
}

extern "C" void kernel_launch(void* const* d_in, const int* in_sizes, int n_in,
                              void* d_out, int out_size)
{
    const int*   bits  = (const int*)  d_in[0];
    const int*   a_idx = (const int*)  d_in[1];
    const float* pre   = (const float*)d_in[4];
    const float* pim   = (const float*)d_in[5];
    const float* nre   = (const float*)d_in[6];
    const float* nim   = (const float*)d_in[7];
    const float* ebno  = (const float*)d_in[8];
    float*       out   = (float*)d_out;

    simplelink_kernel<<<Bn, Tthr>>>(bits, a_idx, pre, pim, nre, nim, ebno, out);
}

// round 10
// speedup vs baseline: 1.6003x; 1.6003x over previous
#include <cuda_runtime.h>

// Problem constants
#define Bn     1024
#define Kc     1056
#define Nc     2112
#define Mc     1056
#define DVc    5
#define NSYMc  528
#define NITERc 20

#define Tthr   352           // threads per block (proven best shape: R6)
#define CPT    3             // check-rows per thread: Mc / Tthr == 3

#define EXCLAMP 0.99999994f  // ~ fp32 rounding of exp(-1e-7): reference saturation

__global__ void __launch_bounds__(Tthr, 2)
simplelink_kernel(const int* __restrict__ bits,
                  const int* __restrict__ a_idx,
                  const float* __restrict__ points_re,
                  const float* __restrict__ points_im,
                  const float* __restrict__ noise_re,
                  const float* __restrict__ noise_im,
                  const float* __restrict__ ebno,
                  float* __restrict__ out)
{
    __shared__ float llr_s[Nc];
    __shared__ float buf0[Kc], buf1[Kc], buf2[Kc];  // info-var marginals, triple-buffered
    __shared__ int   cw_s[Nc];
    __shared__ float pre_s[16], pim_s[16];

    const int b   = blockIdx.x;
    const int tid = threadIdx.x;

    if (tid < 16) { pre_s[tid] = points_re[tid]; pim_s[tid] = points_im[tid]; }

    // ---- load info bits ----
    for (int i = tid; i < Kc; i += Tthr) cw_s[i] = bits[b * Kc + i];
    __syncthreads();

    // ---- LDPC encode: 3 parities per thread ----
    #pragma unroll
    for (int c = 0; c < CPT; c++) {
        int m = tid + c * Tthr;
        const int* row = a_idx + m * DVc;
        int p = 0;
        #pragma unroll
        for (int j = 0; j < DVc; j++) p += cw_s[row[j]];
        cw_s[Kc + m] = p & 1;
    }
    __syncthreads();

    // ---- noise scaling ----
    const float eb    = ebno[0];
    const float no    = __fdiv_rn(1.0f,
                         __fmul_rn(__fmul_rn(powf(10.0f, __fdiv_rn(eb, 10.0f)), 0.5f), 4.0f));
    const float sigma = sqrtf(__fdiv_rn(no, 2.0f));
    const float inv_no = __fdiv_rn(1.0f, no);

    // ---- QAM map + AWGN + APP demap -> llr ----
    for (int s = tid; s < NSYMc; s += Tthr) {
        int sym = (cw_s[4*s] << 3) | (cw_s[4*s+1] << 2) | (cw_s[4*s+2] << 1) | cw_s[4*s+3];
        float yre = pre_s[sym] + sigma * noise_re[b * NSYMc + s];
        float yim = pim_s[sym] + sigma * noise_im[b * NSYMc + s];
        float lg[16];
        #pragma unroll
        for (int i = 0; i < 16; i++) {
            float dr = yre - pre_s[i];
            float di = yim - pim_s[i];
            lg[i] = -(dr * dr + di * di) * inv_no;
        }
        #pragma unroll
        for (int j = 0; j < 4; j++) {
            int sh = 3 - j;
            float m0 = -1e30f, m1 = -1e30f;
            #pragma unroll
            for (int i = 0; i < 16; i++) {
                if ((i >> sh) & 1) m1 = fmaxf(m1, lg[i]);
                else               m0 = fmaxf(m0, lg[i]);
            }
            float s0 = 0.0f, s1 = 0.0f;
            #pragma unroll
            for (int i = 0; i < 16; i++) {
                float e = __expf(lg[i] - (((i >> sh) & 1) ? m1 : m0));
                if ((i >> sh) & 1) s1 += e;
                else               s0 += e;
            }
            llr_s[4*s + j] = (__logf(s0) + m0) - (__logf(s1) + m1);
        }
    }
    __syncthreads();

    // ---- BP setup ----
    int   idx[CPT][DVc];
    float c2v[CPT][DVc];
    float pn5[CPT], pd5[CPT];
    int   psgn[CPT];
    float llr_r[CPT];

    #pragma unroll
    for (int c = 0; c < CPT; c++) {
        int m = tid + c * Tthr;
        const int* row = a_idx + m * DVc;
        #pragma unroll
        for (int j = 0; j < DVc; j++) { idx[c][j] = row[j]; c2v[c][j] = 0.0f; }
        // parity edge: degree-1 variable, v2c = llr_parity forever
        float lp  = llr_s[Kc + m];
        float avp = fminf(fmaxf(fabsf(lp), 1e-6f), 20.0f);
        float ep  = __expf(-avp);
        pn5[c] = 1.0f - ep;
        pd5[c] = 1.0f + ep;
        psgn[c] = (lp < 0.0f) ? 1 : 0;
        llr_r[c] = llr_s[m];
    }

    // pre-init: buf0 = cur at t=0 (marg of c2v=0 is just llr), buf1 = scatter
    // target at t=0. buf2 gets initialized inside iteration t=0.
    #pragma unroll
    for (int c = 0; c < CPT; c++) {
        buf0[tid + c * Tthr] = llr_r[c];
        buf1[tid + c * Tthr] = llr_r[c];
    }
    __syncthreads();

    float* bufs[3] = { buf0, buf1, buf2 };

    // ---- fused BP: 1 phase, 1 barrier per iteration ----
    #pragma unroll 1
    for (int it = 0; it < NITERc; it++) {
        float* cur = bufs[0];
        float* nxt = bufs[1];
        float* nnx = bufs[2];

        // front-batched gather of all marginals this thread needs (MLP=15)
        float tv[CPT][DVc];
        #pragma unroll
        for (int c = 0; c < CPT; c++)
            #pragma unroll
            for (int j = 0; j < DVc; j++)
                tv[c][j] = cur[idx[c][j]];

        // re-init the buffer that becomes the scatter target next iteration
        #pragma unroll
        for (int c = 0; c < CPT; c++) nnx[tid + c * Tthr] = llr_r[c];

        // check-node update + immediate scatter into nxt
        #pragma unroll
        for (int c = 0; c < CPT; c++) {
            float n[DVc], dd[DVc];
            int signs = psgn[c] << DVc;
            #pragma unroll
            for (int j = 0; j < DVc; j++) {
                float v2c = tv[c][j] - c2v[c][j];
                signs |= ((v2c < 0.0f) ? 1 : 0) << j;
                float av = fminf(fmaxf(fabsf(v2c), 1e-6f), 20.0f);
                float e  = __expf(-av);
                n[j]  = 1.0f - e;
                dd[j] = 1.0f + e;
            }
            int totpar = __popc(signs);
            float sN[DVc], sD[DVc];
            float suN = pn5[c], suD = pd5[c];
            #pragma unroll
            for (int j = DVc - 1; j >= 0; j--) {
                sN[j] = suN; sD[j] = suD;
                suN *= n[j]; suD *= dd[j];
            }
            float prN = 1.0f, prD = 1.0f;
            #pragma unroll
            for (int j = 0; j < DVc; j++) {
                float Pn = prN * sN[j];
                float Pd = prD * sD[j];
                Pn = fminf(Pn, EXCLAMP * Pd);
                float dv = __logf(__fdividef(Pd + Pn, Pd - Pn));  // 2*atanh(Pn/Pd)
                int par = (totpar - ((signs >> j) & 1)) & 1;
                float msg = par ? -dv : dv;
                c2v[c][j] = msg;
                atomicAdd(&nxt[idx[c][j]], msg);
                prN *= n[j]; prD *= dd[j];
            }
        }
        __syncthreads();

        // rotate buffers
        float* t0 = bufs[0];
        bufs[0] = bufs[1]; bufs[1] = bufs[2]; bufs[2] = t0;
    }

    // final marginals live in bufs[0] (scatter target of last iteration)
    float* fin = bufs[0];

    // ---- outputs: [bits, bits_rx] each [B,K] float ----
    for (int k = tid; k < Kc; k += Tthr) {
        out[b * Kc + k]           = (float)cw_s[k];
        out[Bn * Kc + b * Kc + k] = (fin[k] < 0.0f) ? 1.0f : 0.0f;
    }
}

extern "C" void kernel_launch(void* const* d_in, const int* in_sizes, int n_in,
                              void* d_out, int out_size)
{
    const int*   bits  = (const int*)  d_in[0];
    const int*   a_idx = (const int*)  d_in[1];
    const float* pre   = (const float*)d_in[4];
    const float* pim   = (const float*)d_in[5];
    const float* nre   = (const float*)d_in[6];
    const float* nim   = (const float*)d_in[7];
    const float* ebno  = (const float*)d_in[8];
    float*       out   = (float*)d_out;

    simplelink_kernel<<<Bn, Tthr>>>(bits, a_idx, pre, pim, nre, nim, ebno, out);
}

// round 11
// speedup vs baseline: 1.9103x; 1.1937x over previous
#include <cuda_runtime.h>

// Problem constants
#define Bn     1024
#define Kc     1056
#define Nc     2112
#define Mc     1056
#define DVc    5
#define Ei     (Mc * DVc)    // 5280 info-bit edges
#define NSYMc  528
#define NITERc 20

#define Tthr   352           // threads per block (proven best shape)
#define CPT    3             // check-rows (and info-vars) per thread

#define EXCLAMP 0.99999994f  // ~ fp32 rounding of exp(-1e-7): reference saturation

// Static edge transpose (graph is shared by all codewords)
__device__ int off_g[Kc + 1];   // variable-major segment starts
__device__ int perm_g[Ei];      // edge (row-major) -> slot (variable-major)

__global__ void __launch_bounds__(1024)
build_transpose_kernel(const int* __restrict__ a_idx)
{
    __shared__ int deg[Kc];
    __shared__ int offs[Kc + 1];
    __shared__ int gsum[34];
    const int t = threadIdx.x;

    for (int i = t; i < Kc; i += 1024) deg[i] = 0;
    __syncthreads();
    for (int e = t; e < Ei; e += 1024) atomicAdd(&deg[a_idx[e]], 1);
    __syncthreads();
    // two-level exclusive scan: 33 groups of 32
    if (t < 33) { int s = 0; for (int i = 0; i < 32; i++) s += deg[t * 32 + i]; gsum[t] = s; }
    __syncthreads();
    if (t == 0) { int s = 0; for (int g = 0; g < 33; g++) { int v = gsum[g]; gsum[g] = s; s += v; } gsum[33] = s; }
    __syncthreads();
    for (int i = t; i < Kc; i += 1024) {
        int g = i >> 5;
        int s = gsum[g];
        for (int k = g << 5; k < i; k++) s += deg[k];
        offs[i] = s;
    }
    if (t == 0) offs[Kc] = gsum[33];
    __syncthreads();
    for (int i = t; i <= Kc; i += 1024) off_g[i] = offs[i];
    // reuse deg as placement cursor
    for (int i = t; i < Kc; i += 1024) deg[i] = offs[i];
    __syncthreads();
    for (int e = t; e < Ei; e += 1024) perm_g[e] = atomicAdd(&deg[a_idx[e]], 1);
}

__global__ void __launch_bounds__(Tthr, 2)
simplelink_kernel(const int* __restrict__ bits,
                  const int* __restrict__ a_idx,
                  const float* __restrict__ points_re,
                  const float* __restrict__ points_im,
                  const float* __restrict__ noise_re,
                  const float* __restrict__ noise_im,
                  const float* __restrict__ ebno,
                  float* __restrict__ out)
{
    __shared__ float llr_s[Nc];
    __shared__ float tot_s[Kc];      // info-var marginals: llr + sum c2v
    __shared__ float c2v_s[Ei];      // c2v messages in variable-major slots
    __shared__ int   cw_s[Nc];
    __shared__ float pre_s[16], pim_s[16];

    const int b   = blockIdx.x;
    const int tid = threadIdx.x;

    if (tid < 16) { pre_s[tid] = points_re[tid]; pim_s[tid] = points_im[tid]; }

    // ---- load info bits ----
    for (int i = tid; i < Kc; i += Tthr) cw_s[i] = bits[b * Kc + i];
    __syncthreads();

    // ---- LDPC encode: 3 parities per thread ----
    #pragma unroll
    for (int c = 0; c < CPT; c++) {
        int m = tid + c * Tthr;
        const int* row = a_idx + m * DVc;
        int p = 0;
        #pragma unroll
        for (int j = 0; j < DVc; j++) p += cw_s[row[j]];
        cw_s[Kc + m] = p & 1;
    }
    __syncthreads();

    // ---- noise scaling ----
    const float eb    = ebno[0];
    const float no    = __fdiv_rn(1.0f,
                         __fmul_rn(__fmul_rn(powf(10.0f, __fdiv_rn(eb, 10.0f)), 0.5f), 4.0f));
    const float sigma = sqrtf(__fdiv_rn(no, 2.0f));
    const float inv_no = __fdiv_rn(1.0f, no);

    // ---- QAM map + AWGN + APP demap -> llr ----
    for (int s = tid; s < NSYMc; s += Tthr) {
        int sym = (cw_s[4*s] << 3) | (cw_s[4*s+1] << 2) | (cw_s[4*s+2] << 1) | cw_s[4*s+3];
        float yre = pre_s[sym] + sigma * noise_re[b * NSYMc + s];
        float yim = pim_s[sym] + sigma * noise_im[b * NSYMc + s];
        float lg[16];
        #pragma unroll
        for (int i = 0; i < 16; i++) {
            float dr = yre - pre_s[i];
            float di = yim - pim_s[i];
            lg[i] = -(dr * dr + di * di) * inv_no;
        }
        #pragma unroll
        for (int j = 0; j < 4; j++) {
            int sh = 3 - j;
            float m0 = -1e30f, m1 = -1e30f;
            #pragma unroll
            for (int i = 0; i < 16; i++) {
                if ((i >> sh) & 1) m1 = fmaxf(m1, lg[i]);
                else               m0 = fmaxf(m0, lg[i]);
            }
            float s0 = 0.0f, s1 = 0.0f;
            #pragma unroll
            for (int i = 0; i < 16; i++) {
                float e = __expf(lg[i] - (((i >> sh) & 1) ? m1 : m0));
                if ((i >> sh) & 1) s1 += e;
                else               s0 += e;
            }
            llr_s[4*s + j] = (__logf(s0) + m0) - (__logf(s1) + m1);
        }
    }
    __syncthreads();

    // ---- BP setup ----
    int   idx[CPT][DVc];   // row -> variable indices
    int   prm[CPT][DVc];   // row-major edge -> variable-major slot
    float c2v[CPT][DVc];
    float pn5[CPT], pd5[CPT];
    int   psgn = 0;
    float llr_r[CPT];
    int   voff[CPT], vdeg[CPT];

    #pragma unroll
    for (int c = 0; c < CPT; c++) {
        int m = tid + c * Tthr;
        const int* row = a_idx  + m * DVc;
        const int* pr  = perm_g + m * DVc;
        #pragma unroll
        for (int j = 0; j < DVc; j++) { idx[c][j] = row[j]; prm[c][j] = pr[j]; c2v[c][j] = 0.0f; }
        // parity edge: degree-1 variable, v2c = llr_parity forever
        float lp  = llr_s[Kc + m];
        float avp = fminf(fmaxf(fabsf(lp), 1e-6f), 20.0f);
        float ep  = __expf(-avp);
        pn5[c] = 1.0f - ep;
        pd5[c] = 1.0f + ep;
        psgn |= ((lp < 0.0f) ? 1 : 0) << c;
        llr_r[c] = llr_s[m];
        int o0 = off_g[m], o1 = off_g[m + 1];
        voff[c] = o0; vdeg[c] = o1 - o0;
    }

    // tot_0 = llr (c2v = 0)
    #pragma unroll
    for (int c = 0; c < CPT; c++) tot_s[tid + c * Tthr] = llr_r[c];
    __syncthreads();

    // ---- BP: CN phase (write c2v slots) / VN phase (contiguous gather) ----
    #pragma unroll 1
    for (int it = 0; it < NITERc; it++) {
        // CN: per-row gather + message computation + slot writes
        #pragma unroll
        for (int c = 0; c < CPT; c++) {
            float n[DVc], dd[DVc];
            int signs = ((psgn >> c) & 1) << DVc;
            #pragma unroll
            for (int j = 0; j < DVc; j++) {
                float v2c = tot_s[idx[c][j]] - c2v[c][j];
                signs |= ((v2c < 0.0f) ? 1 : 0) << j;
                float av = fminf(fmaxf(fabsf(v2c), 1e-6f), 20.0f);
                float e  = __expf(-av);
                n[j]  = 1.0f - e;
                dd[j] = 1.0f + e;
            }
            int totpar = __popc(signs);
            float sN[DVc], sD[DVc];
            float suN = pn5[c], suD = pd5[c];
            #pragma unroll
            for (int j = DVc - 1; j >= 0; j--) {
                sN[j] = suN; sD[j] = suD;
                suN *= n[j]; suD *= dd[j];
            }
            float prN = 1.0f, prD = 1.0f;
            #pragma unroll
            for (int j = 0; j < DVc; j++) {
                float Pn = prN * sN[j];
                float Pd = prD * sD[j];
                Pn = fminf(Pn, EXCLAMP * Pd);
                // 2*atanh(Pn/Pd) = log(Pd+Pn) - log(Pd-Pn)   (no RCP)
                float dv = __logf(Pd + Pn) - __logf(Pd - Pn);
                int par = (totpar - ((signs >> j) & 1)) & 1;
                float msg = par ? -dv : dv;
                c2v[c][j] = msg;
                c2v_s[prm[c][j]] = msg;
                prN *= n[j]; prD *= dd[j];
            }
        }
        __syncthreads();

        // VN: contiguous segment sums -> tot
        #pragma unroll
        for (int c = 0; c < CPT; c++) {
            float acc = llr_r[c];
            int o = voff[c], d = vdeg[c];
            for (int k = 0; k < d; k++) acc += c2v_s[o + k];
            tot_s[tid + c * Tthr] = acc;
        }
        __syncthreads();
    }

    // ---- outputs: [bits, bits_rx] each [B,K] float ----
    for (int k = tid; k < Kc; k += Tthr) {
        out[b * Kc + k]           = (float)cw_s[k];
        out[Bn * Kc + b * Kc + k] = (tot_s[k] < 0.0f) ? 1.0f : 0.0f;
    }
}

extern "C" void kernel_launch(void* const* d_in, const int* in_sizes, int n_in,
                              void* d_out, int out_size)
{
    const int*   bits  = (const int*)  d_in[0];
    const int*   a_idx = (const int*)  d_in[1];
    const float* pre   = (const float*)d_in[4];
    const float* pim   = (const float*)d_in[5];
    const float* nre   = (const float*)d_in[6];
    const float* nim   = (const float*)d_in[7];
    const float* ebno  = (const float*)d_in[8];
    float*       out   = (float*)d_out;

    build_transpose_kernel<<<1, 1024>>>(a_idx);
    simplelink_kernel<<<Bn, Tthr>>>(bits, a_idx, pre, pim, nre, nim, ebno, out);
}

// round 12
// speedup vs baseline: 1.9304x; 1.0105x over previous
#include <cuda_runtime.h>

// Problem constants
#define Bn     1024
#define Kc     1056
#define Nc     2112
#define Mc     1056
#define DVc    5
#define Ei     (Mc * DVc)    // 5280 info-bit edges
#define NSYMc  528
#define NITERc 20

#define Tthr   352           // threads per block
#define CPT    3             // check-rows per thread

#define EXCLAMP 0.99999994f  // ~ fp32 rounding of exp(-1e-7): reference saturation

// SMEM layout (dynamic): [c2v2 | tot2 | cwp | const points]
#define OFF_C2V   0
#define OFF_TOT   (Ei * 8)                       // 42240
#define OFF_CWP   (OFF_TOT + Kc * 8)             // 50688
#define OFF_PTS   (OFF_CWP + Nc * 4)             // 59136
#define SMEM_BYTES (OFF_PTS + 128)               // 59264

// Static edge transpose (graph shared by all codewords)
__device__ int off_g[Kc + 1];
__device__ int perm_g[Ei];

__global__ void __launch_bounds__(1024)
build_transpose_kernel(const int* __restrict__ a_idx)
{
    __shared__ int deg[Kc];
    __shared__ int offs[Kc + 1];
    __shared__ int gsum[34];
    const int t = threadIdx.x;

    for (int i = t; i < Kc; i += 1024) deg[i] = 0;
    __syncthreads();
    for (int e = t; e < Ei; e += 1024) atomicAdd(&deg[a_idx[e]], 1);
    __syncthreads();
    if (t < 33) { int s = 0; for (int i = 0; i < 32; i++) s += deg[t * 32 + i]; gsum[t] = s; }
    __syncthreads();
    if (t == 0) { int s = 0; for (int g = 0; g < 33; g++) { int v = gsum[g]; gsum[g] = s; s += v; } gsum[33] = s; }
    __syncthreads();
    for (int i = t; i < Kc; i += 1024) {
        int g = i >> 5;
        int s = gsum[g];
        for (int k = g << 5; k < i; k++) s += deg[k];
        offs[i] = s;
    }
    if (t == 0) offs[Kc] = gsum[33];
    __syncthreads();
    for (int i = t; i <= Kc; i += 1024) off_g[i] = offs[i];
    for (int i = t; i < Kc; i += 1024) deg[i] = offs[i];
    __syncthreads();
    for (int e = t; e < Ei; e += 1024) perm_g[e] = atomicAdd(&deg[a_idx[e]], 1);
}

// Packed fp32x2 ops (sm_100+; ptxas never auto-generates these)
__device__ __forceinline__ float2 f2mul(float2 a, float2 b) {
    unsigned long long r, x = *(unsigned long long*)&a, y = *(unsigned long long*)&b;
    asm("mul.rn.f32x2 %0, %1, %2;" : "=l"(r) : "l"(x), "l"(y));
    return *(float2*)&r;
}
__device__ __forceinline__ float2 f2add(float2 a, float2 b) {
    unsigned long long r, x = *(unsigned long long*)&a, y = *(unsigned long long*)&b;
    asm("add.rn.f32x2 %0, %1, %2;" : "=l"(r) : "l"(x), "l"(y));
    return *(float2*)&r;
}

__global__ void __launch_bounds__(Tthr, 2)
simplelink_kernel(const int* __restrict__ bits,
                  const int* __restrict__ a_idx,
                  const float* __restrict__ points_re,
                  const float* __restrict__ points_im,
                  const float* __restrict__ noise_re,
                  const float* __restrict__ noise_im,
                  const float* __restrict__ ebno,
                  float* __restrict__ out)
{
    extern __shared__ char smem[];
    float2* c2v2  = (float2*)(smem + OFF_C2V);   // [Ei]  msgs, variable-major slots
    float2* llr2  = (float2*)(smem + OFF_C2V);   // [Nc]  ALIAS: setup lifetime only
    float2* tot2  = (float2*)(smem + OFF_TOT);   // [Kc]  marginals
    int*    cwp   = (int*)   (smem + OFF_CWP);   // [Nc]  bits: cwA | cwB<<8
    float*  pre_s = (float*) (smem + OFF_PTS);
    float*  pim_s = pre_s + 16;

    const int b0  = 2 * blockIdx.x;
    const int tid = threadIdx.x;

    if (tid < 16) { pre_s[tid] = points_re[tid]; pim_s[tid] = points_im[tid]; }

    // ---- load info bits of both codewords, packed ----
    for (int i = tid; i < Kc; i += Tthr)
        cwp[i] = bits[b0 * Kc + i] | (bits[(b0 + 1) * Kc + i] << 8);
    __syncthreads();

    // ---- LDPC encode: 3 parities per thread, both codewords at once ----
    #pragma unroll
    for (int c = 0; c < CPT; c++) {
        int m = tid + c * Tthr;
        const int* row = a_idx + m * DVc;
        int ps = 0;
        #pragma unroll
        for (int j = 0; j < DVc; j++) ps += cwp[row[j]];   // byte fields can't carry (5<256)
        cwp[Kc + m] = (ps & 1) | (((ps >> 8) & 1) << 8);
    }
    __syncthreads();

    // ---- noise scaling ----
    const float eb    = ebno[0];
    const float no    = __fdiv_rn(1.0f,
                         __fmul_rn(__fmul_rn(powf(10.0f, __fdiv_rn(eb, 10.0f)), 0.5f), 4.0f));
    const float sigma = sqrtf(__fdiv_rn(no, 2.0f));
    const float inv_no = __fdiv_rn(1.0f, no);

    // ---- QAM map + AWGN + APP demap for both codewords -> llr2 ----
    for (int s = tid; s < NSYMc; s += Tthr) {
        int p0 = cwp[4*s], p1 = cwp[4*s+1], p2 = cwp[4*s+2], p3 = cwp[4*s+3];
        #pragma unroll
        for (int h = 0; h < 2; h++) {
            int sh8 = 8 * h;
            int sym = (((p0 >> sh8) & 1) << 3) | (((p1 >> sh8) & 1) << 2)
                    | (((p2 >> sh8) & 1) << 1) |  ((p3 >> sh8) & 1);
            float yre = pre_s[sym] + sigma * noise_re[(b0 + h) * NSYMc + s];
            float yim = pim_s[sym] + sigma * noise_im[(b0 + h) * NSYMc + s];
            float lg[16];
            #pragma unroll
            for (int i = 0; i < 16; i++) {
                float dr = yre - pre_s[i];
                float di = yim - pim_s[i];
                lg[i] = -(dr * dr + di * di) * inv_no;
            }
            #pragma unroll
            for (int j = 0; j < 4; j++) {
                int shb = 3 - j;
                float m0 = -1e30f, m1 = -1e30f;
                #pragma unroll
                for (int i = 0; i < 16; i++) {
                    if ((i >> shb) & 1) m1 = fmaxf(m1, lg[i]);
                    else                m0 = fmaxf(m0, lg[i]);
                }
                float s0 = 0.0f, s1 = 0.0f;
                #pragma unroll
                for (int i = 0; i < 16; i++) {
                    float e = __expf(lg[i] - (((i >> shb) & 1) ? m1 : m0));
                    if ((i >> shb) & 1) s1 += e;
                    else                s0 += e;
                }
                ((float*)&llr2[4*s + j])[h] = (__logf(s0) + m0) - (__logf(s1) + m1);
            }
        }
    }
    __syncthreads();

    // ---- BP setup (reads llr2; llr2 dies after this block) ----
    int    ip[CPT][DVc];          // idx | prm<<16
    float2 llr_r2[CPT];
    float2 pn5_2[CPT], pd5_2[CPT];
    int    psA = 0, psB = 0;
    int    voff[CPT], vdeg[CPT];

    #pragma unroll
    for (int c = 0; c < CPT; c++) {
        int m = tid + c * Tthr;
        const int* row = a_idx  + m * DVc;
        const int* pr  = perm_g + m * DVc;
        #pragma unroll
        for (int j = 0; j < DVc; j++) ip[c][j] = row[j] | (pr[j] << 16);
        float2 lp = llr2[Kc + m];
        float aA = fminf(fmaxf(fabsf(lp.x), 1e-6f), 20.0f);
        float aB = fminf(fmaxf(fabsf(lp.y), 1e-6f), 20.0f);
        float eA = __expf(-aA), eB = __expf(-aB);
        pn5_2[c] = make_float2(1.0f - eA, 1.0f - eB);
        pd5_2[c] = make_float2(1.0f + eA, 1.0f + eB);
        psA |= ((lp.x < 0.0f) ? 1 : 0) << c;
        psB |= ((lp.y < 0.0f) ? 1 : 0) << c;
        llr_r2[c] = llr2[m];
        voff[c] = off_g[m];
        vdeg[c] = off_g[m + 1] - voff[c];
    }
    __syncthreads();   // all llr2 reads done; region becomes c2v2

    // zero c2v2 (it=0 reads old messages = 0) and init tot2 = llr
    for (int e = tid; e < Ei; e += Tthr) c2v2[e] = make_float2(0.0f, 0.0f);
    #pragma unroll
    for (int c = 0; c < CPT; c++) tot2[tid + c * Tthr] = llr_r2[c];
    __syncthreads();

    // ---- BP: CN phase / VN phase, both codewords packed ----
    #pragma unroll 1
    for (int it = 0; it < NITERc; it++) {
        #pragma unroll
        for (int c = 0; c < CPT; c++) {
            float2 t2[DVc], co2[DVc];
            #pragma unroll
            for (int j = 0; j < DVc; j++) {
                int e = ip[c][j];
                t2[j]  = tot2[e & 0xFFFF];
                co2[j] = c2v2[e >> 16];
            }
            float2 n2[DVc], d2[DVc];
            int sgA = ((psA >> c) & 1) << DVc;
            int sgB = ((psB >> c) & 1) << DVc;
            #pragma unroll
            for (int j = 0; j < DVc; j++) {
                float vA = t2[j].x - co2[j].x;
                float vB = t2[j].y - co2[j].y;
                sgA |= ((vA < 0.0f) ? 1 : 0) << j;
                sgB |= ((vB < 0.0f) ? 1 : 0) << j;
                float aA = fminf(fmaxf(fabsf(vA), 1e-6f), 20.0f);
                float aB = fminf(fmaxf(fabsf(vB), 1e-6f), 20.0f);
                float eA = __expf(-aA), eB = __expf(-aB);
                n2[j] = make_float2(1.0f - eA, 1.0f - eB);
                d2[j] = make_float2(1.0f + eA, 1.0f + eB);
            }
            int tpA = __popc(sgA), tpB = __popc(sgB);
            float2 sN[DVc], sD[DVc];
            float2 suN = pn5_2[c], suD = pd5_2[c];
            #pragma unroll
            for (int j = DVc - 1; j >= 0; j--) {
                sN[j] = suN; sD[j] = suD;
                suN = f2mul(suN, n2[j]); suD = f2mul(suD, d2[j]);
            }
            float2 prN = make_float2(1.0f, 1.0f), prD = prN;
            #pragma unroll
            for (int j = 0; j < DVc; j++) {
                float2 Pn = f2mul(prN, sN[j]);
                float2 Pd = f2mul(prD, sD[j]);
                float PnA = fminf(Pn.x, EXCLAMP * Pd.x);
                float PnB = fminf(Pn.y, EXCLAMP * Pd.y);
                float dvA = __logf(Pd.x + PnA) - __logf(Pd.x - PnA);  // 2*atanh
                float dvB = __logf(Pd.y + PnB) - __logf(Pd.y - PnB);
                float mA = ((tpA - ((sgA >> j) & 1)) & 1) ? -dvA : dvA;
                float mB = ((tpB - ((sgB >> j) & 1)) & 1) ? -dvB : dvB;
                c2v2[ip[c][j] >> 16] = make_float2(mA, mB);
                prN = f2mul(prN, n2[j]); prD = f2mul(prD, d2[j]);
            }
        }
        __syncthreads();

        // VN: contiguous packed segment sums
        #pragma unroll
        for (int c = 0; c < CPT; c++) {
            float2 acc = llr_r2[c];
            int o = voff[c], d = vdeg[c];
            for (int k = 0; k < d; k++) acc = f2add(acc, c2v2[o + k]);
            tot2[tid + c * Tthr] = acc;
        }
        __syncthreads();
    }

    // ---- outputs: [bits, bits_rx] each [B,K] float; b1 = b0+1 ----
    for (int k = tid; k < Kc; k += Tthr) {
        int pk = cwp[k];
        float2 t = tot2[k];
        out[b0 * Kc + k]                = (float)(pk & 1);
        out[b0 * Kc + Kc + k]           = (float)((pk >> 8) & 1);
        out[Bn * Kc + b0 * Kc + k]      = (t.x < 0.0f) ? 1.0f : 0.0f;
        out[Bn * Kc + b0 * Kc + Kc + k] = (t.y < 0.0f) ? 1.0f : 0.0f;
    }
}

extern "C" void kernel_launch(void* const* d_in, const int* in_sizes, int n_in,
                              void* d_out, int out_size)
{
    const int*   bits  = (const int*)  d_in[0];
    const int*   a_idx = (const int*)  d_in[1];
    const float* pre   = (const float*)d_in[4];
    const float* pim   = (const float*)d_in[5];
    const float* nre   = (const float*)d_in[6];
    const float* nim   = (const float*)d_in[7];
    const float* ebno  = (const float*)d_in[8];
    float*       out   = (float*)d_out;

    cudaFuncSetAttribute(simplelink_kernel,
                         cudaFuncAttributeMaxDynamicSharedMemorySize, SMEM_BYTES);
    build_transpose_kernel<<<1, 1024>>>(a_idx);
    simplelink_kernel<<<Bn / 2, Tthr, SMEM_BYTES>>>(bits, a_idx, pre, pim, nre, nim, ebno, out);
}

// round 13
// speedup vs baseline: 2.2019x; 1.1406x over previous
#include <cuda_runtime.h>

// Problem constants
#define Bn     1024
#define Kc     1056
#define Nc     2112
#define Mc     1056
#define DVc    5
#define Ei     (Mc * DVc)    // 5280 info-bit edges
#define NSYMc  528
#define NITERc 20

#define Tthr   352           // threads per block
#define CPT    3             // check-rows per thread

#define EXCLAMP 0.99999994f  // ~ fp32 rounding of exp(-1e-7): reference saturation
#define LN2F    0.6931471805599453f

// SMEM layout (dynamic): [c2v2 | tot2 | cwp | const points]
#define OFF_C2V   0
#define OFF_TOT   (Ei * 8)                       // 42240
#define OFF_CWP   (OFF_TOT + Kc * 8)             // 50688
#define OFF_PTS   (OFF_CWP + Nc * 4)             // 59136
#define SMEM_BYTES (OFF_PTS + 128)               // 59264

// Static edge transpose (graph shared by all codewords)
__device__ int off_g[Kc + 1];
__device__ int perm_g[Ei];

__global__ void __launch_bounds__(1024)
build_transpose_kernel(const int* __restrict__ a_idx)
{
    __shared__ int deg[Kc];
    __shared__ int offs[Kc + 1];
    __shared__ int gsum[34];
    const int t = threadIdx.x;

    for (int i = t; i < Kc; i += 1024) deg[i] = 0;
    __syncthreads();
    for (int e = t; e < Ei; e += 1024) atomicAdd(&deg[a_idx[e]], 1);
    __syncthreads();
    if (t < 33) { int s = 0; for (int i = 0; i < 32; i++) s += deg[t * 32 + i]; gsum[t] = s; }
    __syncthreads();
    if (t == 0) { int s = 0; for (int g = 0; g < 33; g++) { int v = gsum[g]; gsum[g] = s; s += v; } gsum[33] = s; }
    __syncthreads();
    for (int i = t; i < Kc; i += 1024) {
        int g = i >> 5;
        int s = gsum[g];
        for (int k = g << 5; k < i; k++) s += deg[k];
        offs[i] = s;
    }
    if (t == 0) offs[Kc] = gsum[33];
    __syncthreads();
    for (int i = t; i <= Kc; i += 1024) off_g[i] = offs[i];
    for (int i = t; i < Kc; i += 1024) deg[i] = offs[i];
    __syncthreads();
    for (int e = t; e < Ei; e += 1024) perm_g[e] = atomicAdd(&deg[a_idx[e]], 1);
}

// Packed fp32x2 ops (sm_100+; ptxas never auto-generates these)
__device__ __forceinline__ float2 f2mul(float2 a, float2 b) {
    unsigned long long r, x = *(unsigned long long*)&a, y = *(unsigned long long*)&b;
    asm("mul.rn.f32x2 %0, %1, %2;" : "=l"(r) : "l"(x), "l"(y));
    return *(float2*)&r;
}
__device__ __forceinline__ float2 f2add(float2 a, float2 b) {
    unsigned long long r, x = *(unsigned long long*)&a, y = *(unsigned long long*)&b;
    asm("add.rn.f32x2 %0, %1, %2;" : "=l"(r) : "l"(x), "l"(y));
    return *(float2*)&r;
}
__device__ __forceinline__ float2 f2fma(float2 a, float2 b, float2 c) {
    unsigned long long r, x = *(unsigned long long*)&a, y = *(unsigned long long*)&b,
                       z = *(unsigned long long*)&c;
    asm("fma.rn.f32x2 %0, %1, %2, %3;" : "=l"(r) : "l"(x), "l"(y), "l"(z));
    return *(float2*)&r;
}

__global__ void __launch_bounds__(Tthr, 2)
simplelink_kernel(const int* __restrict__ bits,
                  const int* __restrict__ a_idx,
                  const float* __restrict__ points_re,
                  const float* __restrict__ points_im,
                  const float* __restrict__ noise_re,
                  const float* __restrict__ noise_im,
                  const float* __restrict__ ebno,
                  float* __restrict__ out)
{
    extern __shared__ char smem[];
    float2* c2v2  = (float2*)(smem + OFF_C2V);   // [Ei]  msgs, variable-major slots
    float2* llr2  = (float2*)(smem + OFF_C2V);   // [Nc]  ALIAS: setup lifetime only
    float2* tot2  = (float2*)(smem + OFF_TOT);   // [Kc]  marginals
    int*    cwp   = (int*)   (smem + OFF_CWP);   // [Nc]  bits: cwA | cwB<<8
    float*  pre_s = (float*) (smem + OFF_PTS);
    float*  pim_s = pre_s + 16;

    const int b0  = 2 * blockIdx.x;
    const int tid = threadIdx.x;

    if (tid < 16) { pre_s[tid] = points_re[tid]; pim_s[tid] = points_im[tid]; }

    // ---- load info bits of both codewords, packed ----
    for (int i = tid; i < Kc; i += Tthr)
        cwp[i] = bits[b0 * Kc + i] | (bits[(b0 + 1) * Kc + i] << 8);
    __syncthreads();

    // ---- LDPC encode: 3 parities per thread, both codewords at once ----
    #pragma unroll
    for (int c = 0; c < CPT; c++) {
        int m = tid + c * Tthr;
        const int* row = a_idx + m * DVc;
        int ps = 0;
        #pragma unroll
        for (int j = 0; j < DVc; j++) ps += cwp[row[j]];   // byte fields can't carry (5<256)
        cwp[Kc + m] = (ps & 1) | (((ps >> 8) & 1) << 8);
    }
    __syncthreads();

    // ---- noise scaling ----
    const float eb    = ebno[0];
    const float no    = __fdiv_rn(1.0f,
                         __fmul_rn(__fmul_rn(powf(10.0f, __fdiv_rn(eb, 10.0f)), 0.5f), 4.0f));
    const float sigma = sqrtf(__fdiv_rn(no, 2.0f));
    const float inv_no = __fdiv_rn(1.0f, no);

    // ---- QAM map + AWGN + APP demap for both codewords -> llr2 ----
    for (int s = tid; s < NSYMc; s += Tthr) {
        int p0 = cwp[4*s], p1 = cwp[4*s+1], p2 = cwp[4*s+2], p3 = cwp[4*s+3];
        #pragma unroll
        for (int h = 0; h < 2; h++) {
            int sh8 = 8 * h;
            int sym = (((p0 >> sh8) & 1) << 3) | (((p1 >> sh8) & 1) << 2)
                    | (((p2 >> sh8) & 1) << 1) |  ((p3 >> sh8) & 1);
            float yre = pre_s[sym] + sigma * noise_re[(b0 + h) * NSYMc + s];
            float yim = pim_s[sym] + sigma * noise_im[(b0 + h) * NSYMc + s];
            float lg[16];
            #pragma unroll
            for (int i = 0; i < 16; i++) {
                float dr = yre - pre_s[i];
                float di = yim - pim_s[i];
                lg[i] = -(dr * dr + di * di) * inv_no;
            }
            #pragma unroll
            for (int j = 0; j < 4; j++) {
                int shb = 3 - j;
                float m0 = -1e30f, m1 = -1e30f;
                #pragma unroll
                for (int i = 0; i < 16; i++) {
                    if ((i >> shb) & 1) m1 = fmaxf(m1, lg[i]);
                    else                m0 = fmaxf(m0, lg[i]);
                }
                float s0 = 0.0f, s1 = 0.0f;
                #pragma unroll
                for (int i = 0; i < 16; i++) {
                    float e = __expf(lg[i] - (((i >> shb) & 1) ? m1 : m0));
                    if ((i >> shb) & 1) s1 += e;
                    else                s0 += e;
                }
                ((float*)&llr2[4*s + j])[h] = (__logf(s0) + m0) - (__logf(s1) + m1);
            }
        }
    }
    __syncthreads();

    // ---- BP setup (reads llr2; llr2 dies after this block) ----
    int    ip[CPT][DVc];          // idx | prm<<16
    float2 llr_r2[CPT];
    float2 pn5_2[CPT], pd5_2[CPT];   // SIGNED parity-edge numerator, denominator
    int    voff[CPT], vdeg[CPT];

    #pragma unroll
    for (int c = 0; c < CPT; c++) {
        int m = tid + c * Tthr;
        const int* row = a_idx  + m * DVc;
        const int* pr  = perm_g + m * DVc;
        #pragma unroll
        for (int j = 0; j < DVc; j++) ip[c][j] = row[j] | (pr[j] << 16);
        float2 lp = llr2[Kc + m];
        float eA = __expf(-fabsf(lp.x));
        float eB = __expf(-fabsf(lp.y));
        pn5_2[c] = make_float2(copysignf(1.0f - eA, lp.x), copysignf(1.0f - eB, lp.y));
        pd5_2[c] = make_float2(1.0f + eA, 1.0f + eB);
        llr_r2[c] = llr2[m];
        voff[c] = off_g[m];
        vdeg[c] = off_g[m + 1] - voff[c];
    }
    __syncthreads();   // all llr2 reads done; region becomes c2v2

    // zero c2v2 (it=0 reads old messages = 0) and init tot2 = llr
    for (int e = tid; e < Ei; e += Tthr) c2v2[e] = make_float2(0.0f, 0.0f);
    #pragma unroll
    for (int c = 0; c < CPT; c++) tot2[tid + c * Tthr] = llr_r2[c];
    __syncthreads();

    const float2 one2  = make_float2(1.0f, 1.0f);
    const float2 mone2 = make_float2(-1.0f, -1.0f);
    const float2 ex2   = make_float2(EXCLAMP, EXCLAMP);

    // ---- BP: CN phase / VN phase, both codewords packed ----
    #pragma unroll 1
    for (int it = 0; it < NITERc; it++) {
        #pragma unroll
        for (int c = 0; c < CPT; c++) {
            float2 nv[DVc], dv2[DVc];
            #pragma unroll
            for (int j = 0; j < DVc; j++) {
                int e = ip[c][j];
                float2 t2 = tot2[e & 0xFFFF];
                float2 co = c2v2[e >> 16];
                float2 v  = f2fma(co, mone2, t2);          // v2c = tot - c2v
                float eA = __expf(-fabsf(v.x));
                float eB = __expf(-fabsf(v.y));
                // signed numerator: sign rides the product; 2atanh is odd
                nv[j]  = make_float2(copysignf(1.0f - eA, v.x),
                                     copysignf(1.0f - eB, v.y));
                dv2[j] = make_float2(1.0f + eA, 1.0f + eB);
            }
            // suffix products seeded with (signed) parity-edge constants
            float2 sN[DVc], sD[DVc];
            float2 suN = pn5_2[c], suD = pd5_2[c];
            #pragma unroll
            for (int j = DVc - 1; j >= 0; j--) {
                sN[j] = suN; sD[j] = suD;
                suN = f2mul(suN, nv[j]); suD = f2mul(suD, dv2[j]);
            }
            float2 prN = one2, prD = one2;
            #pragma unroll
            for (int j = 0; j < DVc; j++) {
                float2 Pn = f2mul(prN, sN[j]);
                float2 Pd = f2mul(prD, sD[j]);
                float2 lim = f2mul(Pd, ex2);
                float PnA = fmaxf(fminf(Pn.x, lim.x), -lim.x);
                float PnB = fmaxf(fminf(Pn.y, lim.y), -lim.y);
                float2 Pnc = make_float2(PnA, PnB);
                float2 a2 = f2add(Pd, Pnc);                 // Pd + Pn
                float2 b2 = f2fma(Pnc, mone2, Pd);          // Pd - Pn
                // dv = ln2*(lg2(a)-lg2(b)) = 2*atanh(Pn/Pd), sign automatic
                float mA = LN2F * (__log2f(a2.x) - __log2f(b2.x));
                float mB = LN2F * (__log2f(a2.y) - __log2f(b2.y));
                c2v2[ip[c][j] >> 16] = make_float2(mA, mB);
                prN = f2mul(prN, nv[j]); prD = f2mul(prD, dv2[j]);
            }
        }
        __syncthreads();

        // VN: contiguous packed segment sums
        #pragma unroll
        for (int c = 0; c < CPT; c++) {
            float2 acc = llr_r2[c];
            int o = voff[c], d = vdeg[c];
            for (int k = 0; k < d; k++) acc = f2add(acc, c2v2[o + k]);
            tot2[tid + c * Tthr] = acc;
        }
        __syncthreads();
    }

    // ---- outputs: [bits, bits_rx] each [B,K] float; b1 = b0+1 ----
    for (int k = tid; k < Kc; k += Tthr) {
        int pk = cwp[k];
        float2 t = tot2[k];
        out[b0 * Kc + k]                = (float)(pk & 1);
        out[b0 * Kc + Kc + k]           = (float)((pk >> 8) & 1);
        out[Bn * Kc + b0 * Kc + k]      = (t.x < 0.0f) ? 1.0f : 0.0f;
        out[Bn * Kc + b0 * Kc + Kc + k] = (t.y < 0.0f) ? 1.0f : 0.0f;
    }
}

extern "C" void kernel_launch(void* const* d_in, const int* in_sizes, int n_in,
                              void* d_out, int out_size)
{
    const int*   bits  = (const int*)  d_in[0];
    const int*   a_idx = (const int*)  d_in[1];
    const float* pre   = (const float*)d_in[4];
    const float* pim   = (const float*)d_in[5];
    const float* nre   = (const float*)d_in[6];
    const float* nim   = (const float*)d_in[7];
    const float* ebno  = (const float*)d_in[8];
    float*       out   = (float*)d_out;

    cudaFuncSetAttribute(simplelink_kernel,
                         cudaFuncAttributeMaxDynamicSharedMemorySize, SMEM_BYTES);
    build_transpose_kernel<<<1, 1024>>>(a_idx);
    simplelink_kernel<<<Bn / 2, Tthr, SMEM_BYTES>>>(bits, a_idx, pre, pim, nre, nim, ebno, out);
}

// round 15
// speedup vs baseline: 2.4280x; 1.1027x over previous
#include <cuda_runtime.h>

// Problem constants
#define Bn     1024
#define Kc     1056
#define Nc     2112
#define Mc     1056
#define DVc    5
#define Ei     (Mc * DVc)    // 5280 info-bit edges
#define NSYMc  528
#define NITERc 20

#define Tthr   352           // threads per block
#define CPT    3             // check-rows per thread

#define LN2F    0.6931471805599453f
#define SATR    3e-8f        // b >= SATR*a  ->  dv <= ln(1/SATR) ~ 17.3 (ref saturation)
#define TINYF   1e-35f

// SMEM layout (dynamic): [c2v2 | tot2 | cwp | const points]
#define OFF_C2V   0
#define OFF_TOT   (Ei * 8)                       // 42240
#define OFF_CWP   (OFF_TOT + Kc * 8)             // 50688
#define OFF_PTS   (OFF_CWP + Nc * 4)             // 59136
#define SMEM_BYTES (OFF_PTS + 128)               // 59264

// Static edge transpose (graph shared by all codewords)
__device__ int off_g[Kc + 1];
__device__ int perm_g[Ei];

__global__ void __launch_bounds__(1024)
build_transpose_kernel(const int* __restrict__ a_idx)
{
    __shared__ int deg[Kc];
    __shared__ int offs[Kc + 1];
    __shared__ int gsum[34];
    const int t = threadIdx.x;

    for (int i = t; i < Kc; i += 1024) deg[i] = 0;
    __syncthreads();
    for (int e = t; e < Ei; e += 1024) atomicAdd(&deg[a_idx[e]], 1);
    __syncthreads();
    if (t < 33) { int s = 0; for (int i = 0; i < 32; i++) s += deg[t * 32 + i]; gsum[t] = s; }
    __syncthreads();
    if (t == 0) { int s = 0; for (int g = 0; g < 33; g++) { int v = gsum[g]; gsum[g] = s; s += v; } gsum[33] = s; }
    __syncthreads();
    for (int i = t; i < Kc; i += 1024) {
        int g = i >> 5;
        int s = gsum[g];
        for (int k = g << 5; k < i; k++) s += deg[k];
        offs[i] = s;
    }
    if (t == 0) offs[Kc] = gsum[33];
    __syncthreads();
    for (int i = t; i <= Kc; i += 1024) off_g[i] = offs[i];
    for (int i = t; i < Kc; i += 1024) deg[i] = offs[i];
    __syncthreads();
    for (int e = t; e < Ei; e += 1024) perm_g[e] = atomicAdd(&deg[a_idx[e]], 1);
}

// Packed fp32x2 ops (sm_100+; ptxas never auto-generates these)
__device__ __forceinline__ float2 f2mul(float2 a, float2 b) {
    unsigned long long r, x = *(unsigned long long*)&a, y = *(unsigned long long*)&b;
    asm("mul.rn.f32x2 %0, %1, %2;" : "=l"(r) : "l"(x), "l"(y));
    return *(float2*)&r;
}
__device__ __forceinline__ float2 f2add(float2 a, float2 b) {
    unsigned long long r, x = *(unsigned long long*)&a, y = *(unsigned long long*)&b;
    asm("add.rn.f32x2 %0, %1, %2;" : "=l"(r) : "l"(x), "l"(y));
    return *(float2*)&r;
}
__device__ __forceinline__ float2 f2sub(float2 a, float2 b) {
    return f2add(a, make_float2(-b.x, -b.y));
}
__device__ __forceinline__ float ftanh(float x) {
    float r;
    asm("tanh.approx.f32 %0, %1;" : "=f"(r) : "f"(x));
    return r;
}

__global__ void __launch_bounds__(Tthr, 2)
simplelink_kernel(const int* __restrict__ bits,
                  const int* __restrict__ a_idx,
                  const float* __restrict__ points_re,
                  const float* __restrict__ points_im,
                  const float* __restrict__ noise_re,
                  const float* __restrict__ noise_im,
                  const float* __restrict__ ebno,
                  float* __restrict__ out)
{
    extern __shared__ char smem[];
    float2* c2v2  = (float2*)(smem + OFF_C2V);   // [Ei]  msgs, variable-major slots
    float2* llr2  = (float2*)(smem + OFF_C2V);   // [Nc]  ALIAS: setup lifetime only
    float2* tot2  = (float2*)(smem + OFF_TOT);   // [Kc]  marginals
    int*    cwp   = (int*)   (smem + OFF_CWP);   // [Nc]  bits: cwA | cwB<<8
    float*  pre_s = (float*) (smem + OFF_PTS);
    float*  pim_s = pre_s + 16;

    const int b0  = 2 * blockIdx.x;
    const int tid = threadIdx.x;

    if (tid < 16) { pre_s[tid] = points_re[tid]; pim_s[tid] = points_im[tid]; }

    // ---- load info bits of both codewords, packed ----
    for (int i = tid; i < Kc; i += Tthr)
        cwp[i] = bits[b0 * Kc + i] | (bits[(b0 + 1) * Kc + i] << 8);
    __syncthreads();

    // ---- LDPC encode: 3 parities per thread, both codewords at once ----
    #pragma unroll
    for (int c = 0; c < CPT; c++) {
        int m = tid + c * Tthr;
        const int* row = a_idx + m * DVc;
        int ps = 0;
        #pragma unroll
        for (int j = 0; j < DVc; j++) ps += cwp[row[j]];   // byte fields can't carry (5<256)
        cwp[Kc + m] = (ps & 1) | (((ps >> 8) & 1) << 8);
    }
    __syncthreads();

    // ---- noise scaling ----
    const float eb    = ebno[0];
    const float no    = __fdiv_rn(1.0f,
                         __fmul_rn(__fmul_rn(powf(10.0f, __fdiv_rn(eb, 10.0f)), 0.5f), 4.0f));
    const float sigma = sqrtf(__fdiv_rn(no, 2.0f));
    const float inv_no = __fdiv_rn(1.0f, no);

    // ---- QAM map + AWGN + APP demap for both codewords -> llr2 ----
    for (int s = tid; s < NSYMc; s += Tthr) {
        int p0 = cwp[4*s], p1 = cwp[4*s+1], p2 = cwp[4*s+2], p3 = cwp[4*s+3];
        #pragma unroll
        for (int h = 0; h < 2; h++) {
            int sh8 = 8 * h;
            int sym = (((p0 >> sh8) & 1) << 3) | (((p1 >> sh8) & 1) << 2)
                    | (((p2 >> sh8) & 1) << 1) |  ((p3 >> sh8) & 1);
            float yre = pre_s[sym] + sigma * noise_re[(b0 + h) * NSYMc + s];
            float yim = pim_s[sym] + sigma * noise_im[(b0 + h) * NSYMc + s];
            float lg[16];
            #pragma unroll
            for (int i = 0; i < 16; i++) {
                float dr = yre - pre_s[i];
                float di = yim - pim_s[i];
                lg[i] = -(dr * dr + di * di) * inv_no;
            }
            #pragma unroll
            for (int j = 0; j < 4; j++) {
                int shb = 3 - j;
                float m0 = -1e30f, m1 = -1e30f;
                #pragma unroll
                for (int i = 0; i < 16; i++) {
                    if ((i >> shb) & 1) m1 = fmaxf(m1, lg[i]);
                    else                m0 = fmaxf(m0, lg[i]);
                }
                float s0 = 0.0f, s1 = 0.0f;
                #pragma unroll
                for (int i = 0; i < 16; i++) {
                    float e = __expf(lg[i] - (((i >> shb) & 1) ? m1 : m0));
                    if ((i >> shb) & 1) s1 += e;
                    else                s0 += e;
                }
                ((float*)&llr2[4*s + j])[h] = (__logf(s0) + m0) - (__logf(s1) + m1);
            }
        }
    }
    __syncthreads();

    // ---- BP setup (reads llr2; llr2 dies at first CN write) ----
    int    ip[CPT][DVc];          // idx | prm<<16
    float2 c2vr[CPT][DVc];        // old messages, register-resident
    float2 llr_r2[CPT];
    float2 t5[CPT];               // parity-edge tanh factor (signed, constant)
    int    voff[CPT], vdeg[CPT];

    #pragma unroll
    for (int c = 0; c < CPT; c++) {
        int m = tid + c * Tthr;
        const int* row = a_idx  + m * DVc;
        const int* pr  = perm_g + m * DVc;
        #pragma unroll
        for (int j = 0; j < DVc; j++) {
            ip[c][j] = row[j] | (pr[j] << 16);
            c2vr[c][j] = make_float2(0.0f, 0.0f);
        }
        float2 lp = llr2[Kc + m];
        t5[c] = make_float2(ftanh(0.5f * lp.x), ftanh(0.5f * lp.y));
        llr_r2[c] = llr2[m];
        voff[c] = off_g[m];
        vdeg[c] = off_g[m + 1] - voff[c];
    }
    __syncthreads();   // all llr2 reads done; region becomes c2v2

    // tot_0 = llr (c2v = 0). c2v2 needs no init: CN writes every slot before VN reads.
    #pragma unroll
    for (int c = 0; c < CPT; c++) tot2[tid + c * Tthr] = llr_r2[c];
    __syncthreads();

    const float2 half2 = make_float2(0.5f, 0.5f);
    const float2 ln2_2 = make_float2(LN2F, LN2F);

    // ---- BP: CN phase / VN phase, both codewords packed ----
    #pragma unroll 1
    for (int it = 0; it < NITERc; it++) {
        #pragma unroll
        for (int c = 0; c < CPT; c++) {
            float2 t[DVc];
            // gather + tanh factors (signed)
            #pragma unroll
            for (int j = 0; j < DVc; j++) {
                float2 tt = tot2[ip[c][j] & 0xFFFF];
                float2 v  = f2sub(tt, c2vr[c][j]);
                float2 hv = f2mul(v, half2);
                t[j] = make_float2(ftanh(hv.x), ftanh(hv.y));
            }
            // full product incl. parity factor
            float2 R = t5[c];
            #pragma unroll
            for (int j = 0; j < DVc; j++) R = f2mul(R, t[j]);
            // per-edge: dv = ln2*(lg2|t+R| - lg2|t-R|) = 2*atanh(R/t), sign automatic
            #pragma unroll
            for (int j = 0; j < DVc; j++) {
                float2 a2 = f2add(t[j], R);
                float2 b2 = f2sub(t[j], R);
                float aA = fmaxf(fabsf(a2.x), TINYF);
                float aB = fmaxf(fabsf(a2.y), TINYF);
                float bA = fmaxf(fabsf(b2.x), fmaxf(SATR * aA, TINYF));
                float bB = fmaxf(fabsf(b2.y), fmaxf(SATR * aB, TINYF));
                float2 lgd = make_float2(__log2f(aA) - __log2f(bA),
                                         __log2f(aB) - __log2f(bB));
                float2 msg = f2mul(lgd, ln2_2);
                c2vr[c][j] = msg;
                c2v2[ip[c][j] >> 16] = msg;
            }
        }
        __syncthreads();

        // VN: contiguous packed segment sums
        #pragma unroll
        for (int c = 0; c < CPT; c++) {
            float2 acc = llr_r2[c];
            int o = voff[c], d = vdeg[c];
            for (int k = 0; k < d; k++) acc = f2add(acc, c2v2[o + k]);
            tot2[tid + c * Tthr] = acc;
        }
        __syncthreads();
    }

    // ---- outputs: [bits, bits_rx] each [B,K] float; b1 = b0+1 ----
    for (int k = tid; k < Kc; k += Tthr) {
        int pk = cwp[k];
        float2 t = tot2[k];
        out[b0 * Kc + k]                = (float)(pk & 1);
        out[b0 * Kc + Kc + k]           = (float)((pk >> 8) & 1);
        out[Bn * Kc + b0 * Kc + k]      = (t.x < 0.0f) ? 1.0f : 0.0f;
        out[Bn * Kc + b0 * Kc + Kc + k] = (t.y < 0.0f) ? 1.0f : 0.0f;
    }
}

extern "C" void kernel_launch(void* const* d_in, const int* in_sizes, int n_in,
                              void* d_out, int out_size)
{
    const int*   bits  = (const int*)  d_in[0];
    const int*   a_idx = (const int*)  d_in[1];
    const float* pre   = (const float*)d_in[4];
    const float* pim   = (const float*)d_in[5];
    const float* nre   = (const float*)d_in[6];
    const float* nim   = (const float*)d_in[7];
    const float* ebno  = (const float*)d_in[8];
    float*       out   = (float*)d_out;

    cudaFuncSetAttribute(simplelink_kernel,
                         cudaFuncAttributeMaxDynamicSharedMemorySize, SMEM_BYTES);
    build_transpose_kernel<<<1, 1024>>>(a_idx);
    simplelink_kernel<<<Bn / 2, Tthr, SMEM_BYTES>>>(bits, a_idx, pre, pim, nre, nim, ebno, out);
}

// round 17
// speedup vs baseline: 2.4487x; 1.0085x over previous
#include <cuda_runtime.h>

// Problem constants
#define Bn     1024
#define Kc     1056
#define Nc     2112
#define Mc     1056
#define DVc    5
#define Ei     (Mc * DVc)    // 5280 info-bit edges
#define NSYMc  528
#define NITERc 20

#define Tthr   352           // threads per block
#define CPT    3             // check-rows per thread

#define LN2F    0.6931471805599453f
#define SATR    3e-8f        // b >= SATR*a  ->  dv <= ln(1/SATR) ~ 17.3 (ref saturation)
#define TINYF   1e-35f

// SMEM layout (dynamic): [c2v2 | tot2 | cwp | const points]
#define OFF_C2V   0
#define OFF_TOT   (Ei * 8)                       // 42240
#define OFF_CWP   (OFF_TOT + Kc * 8)             // 50688
#define OFF_PTS   (OFF_CWP + Nc * 4)             // 59136
#define SMEM_BYTES (OFF_PTS + 128)               // 59264

// Static edge transpose (graph shared by all codewords)
__device__ int off_g[Kc + 1];
__device__ int perm_g[Ei];

__global__ void __launch_bounds__(1024)
build_transpose_kernel(const int* __restrict__ a_idx)
{
    __shared__ int deg[Kc];
    __shared__ int offs[Kc + 1];
    __shared__ int gsum[34];
    const int t = threadIdx.x;

    for (int i = t; i < Kc; i += 1024) deg[i] = 0;
    __syncthreads();
    for (int e = t; e < Ei; e += 1024) atomicAdd(&deg[a_idx[e]], 1);
    __syncthreads();
    if (t < 33) { int s = 0; for (int i = 0; i < 32; i++) s += deg[t * 32 + i]; gsum[t] = s; }
    __syncthreads();
    if (t == 0) { int s = 0; for (int g = 0; g < 33; g++) { int v = gsum[g]; gsum[g] = s; s += v; } gsum[33] = s; }
    __syncthreads();
    for (int i = t; i < Kc; i += 1024) {
        int g = i >> 5;
        int s = gsum[g];
        for (int k = g << 5; k < i; k++) s += deg[k];
        offs[i] = s;
    }
    if (t == 0) offs[Kc] = gsum[33];
    __syncthreads();
    for (int i = t; i <= Kc; i += 1024) off_g[i] = offs[i];
    for (int i = t; i < Kc; i += 1024) deg[i] = offs[i];
    __syncthreads();
    for (int e = t; e < Ei; e += 1024) perm_g[e] = atomicAdd(&deg[a_idx[e]], 1);
}

// Packed fp32x2 ops (sm_100+; ptxas never auto-generates these)
__device__ __forceinline__ float2 f2mul(float2 a, float2 b) {
    unsigned long long r, x = *(unsigned long long*)&a, y = *(unsigned long long*)&b;
    asm("mul.rn.f32x2 %0, %1, %2;" : "=l"(r) : "l"(x), "l"(y));
    return *(float2*)&r;
}
__device__ __forceinline__ float2 f2add(float2 a, float2 b) {
    unsigned long long r, x = *(unsigned long long*)&a, y = *(unsigned long long*)&b;
    asm("add.rn.f32x2 %0, %1, %2;" : "=l"(r) : "l"(x), "l"(y));
    return *(float2*)&r;
}
__device__ __forceinline__ float2 f2sub(float2 a, float2 b) {
    return f2add(a, make_float2(-b.x, -b.y));
}
__device__ __forceinline__ float ftanh(float x) {
    float r;
    asm("tanh.approx.f32 %0, %1;" : "=f"(r) : "f"(x));
    return r;
}

__global__ void __launch_bounds__(Tthr, 2)
simplelink_kernel(const int* __restrict__ bits,
                  const int* __restrict__ a_idx,
                  const float* __restrict__ points_re,
                  const float* __restrict__ points_im,
                  const float* __restrict__ noise_re,
                  const float* __restrict__ noise_im,
                  const float* __restrict__ ebno,
                  float* __restrict__ out)
{
    extern __shared__ char smem[];
    float2* c2v2  = (float2*)(smem + OFF_C2V);   // [Ei]  msgs, variable-major slots
    float2* llr2  = (float2*)(smem + OFF_C2V);   // [Nc]  ALIAS: setup lifetime only
    float2* tot2  = (float2*)(smem + OFF_TOT);   // [Kc]  marginals
    int*    cwp   = (int*)   (smem + OFF_CWP);   // [Nc]  bits: cwA | cwB<<8
    float*  pre_s = (float*) (smem + OFF_PTS);
    float*  pim_s = pre_s + 16;

    const int b0  = 2 * blockIdx.x;
    const int tid = threadIdx.x;

    if (tid < 16) { pre_s[tid] = points_re[tid]; pim_s[tid] = points_im[tid]; }

    // ---- load info bits of both codewords, packed ----
    for (int i = tid; i < Kc; i += Tthr)
        cwp[i] = bits[b0 * Kc + i] | (bits[(b0 + 1) * Kc + i] << 8);
    __syncthreads();

    // ---- LDPC encode: 3 parities per thread, both codewords at once ----
    #pragma unroll
    for (int c = 0; c < CPT; c++) {
        int m = tid + c * Tthr;
        const int* row = a_idx + m * DVc;
        int ps = 0;
        #pragma unroll
        for (int j = 0; j < DVc; j++) ps += cwp[row[j]];   // byte fields can't carry (5<256)
        cwp[Kc + m] = (ps & 1) | (((ps >> 8) & 1) << 8);
    }
    __syncthreads();

    // ---- noise scaling ----
    const float eb    = ebno[0];
    const float no    = __fdiv_rn(1.0f,
                         __fmul_rn(__fmul_rn(powf(10.0f, __fdiv_rn(eb, 10.0f)), 0.5f), 4.0f));
    const float sigma = sqrtf(__fdiv_rn(no, 2.0f));
    const float inv_no = __fdiv_rn(1.0f, no);

    // ---- QAM map + AWGN + APP demap for both codewords -> llr2 ----
    for (int s = tid; s < NSYMc; s += Tthr) {
        int p0 = cwp[4*s], p1 = cwp[4*s+1], p2 = cwp[4*s+2], p3 = cwp[4*s+3];
        #pragma unroll
        for (int h = 0; h < 2; h++) {
            int sh8 = 8 * h;
            int sym = (((p0 >> sh8) & 1) << 3) | (((p1 >> sh8) & 1) << 2)
                    | (((p2 >> sh8) & 1) << 1) |  ((p3 >> sh8) & 1);
            float yre = pre_s[sym] + sigma * noise_re[(b0 + h) * NSYMc + s];
            float yim = pim_s[sym] + sigma * noise_im[(b0 + h) * NSYMc + s];
            float lg[16];
            #pragma unroll
            for (int i = 0; i < 16; i++) {
                float dr = yre - pre_s[i];
                float di = yim - pim_s[i];
                lg[i] = -(dr * dr + di * di) * inv_no;
            }
            #pragma unroll
            for (int j = 0; j < 4; j++) {
                int shb = 3 - j;
                float m0 = -1e30f, m1 = -1e30f;
                #pragma unroll
                for (int i = 0; i < 16; i++) {
                    if ((i >> shb) & 1) m1 = fmaxf(m1, lg[i]);
                    else                m0 = fmaxf(m0, lg[i]);
                }
                float s0 = 0.0f, s1 = 0.0f;
                #pragma unroll
                for (int i = 0; i < 16; i++) {
                    float e = __expf(lg[i] - (((i >> shb) & 1) ? m1 : m0));
                    if ((i >> shb) & 1) s1 += e;
                    else                s0 += e;
                }
                ((float*)&llr2[4*s + j])[h] = (__logf(s0) + m0) - (__logf(s1) + m1);
            }
        }
    }
    __syncthreads();

    // ---- BP setup (reads llr2; llr2 dies at first CN write) ----
    int    ip[CPT][DVc];          // idx | prm<<16
    float2 c2vr[CPT][DVc];        // old messages, register-resident
    float2 llr_r2[CPT];
    float2 t5[CPT];               // parity-edge tanh factor (signed, constant)
    int    voff[CPT], vdeg[CPT];

    #pragma unroll
    for (int c = 0; c < CPT; c++) {
        int m = tid + c * Tthr;
        const int* row = a_idx  + m * DVc;
        const int* pr  = perm_g + m * DVc;
        #pragma unroll
        for (int j = 0; j < DVc; j++) {
            ip[c][j] = row[j] | (pr[j] << 16);
            c2vr[c][j] = make_float2(0.0f, 0.0f);
        }
        float2 lp = llr2[Kc + m];
        t5[c] = make_float2(ftanh(0.5f * lp.x), ftanh(0.5f * lp.y));
        llr_r2[c] = llr2[m];
        voff[c] = off_g[m];
        vdeg[c] = off_g[m + 1] - voff[c];
    }
    __syncthreads();   // all llr2 reads done; region becomes c2v2

    // tot_0 = llr (c2v = 0). c2v2 needs no init: CN writes every slot before VN reads.
    #pragma unroll
    for (int c = 0; c < CPT; c++) tot2[tid + c * Tthr] = llr_r2[c];
    __syncthreads();

    const float2 half2c = make_float2(0.5f, 0.5f);
    const float2 ln2_2  = make_float2(LN2F, LN2F);

    // ---- BP: CN phase / VN phase, early exit on 2x-stable syndrome ----
    int prevStable = 0;
    #pragma unroll 1
    for (int it = 0; it < NITERc; it++) {
        int pred = 1;   // all my rows' checks satisfied (both codewords)?
        #pragma unroll
        for (int c = 0; c < CPT; c++) {
            float2 t[DVc];
            // gather + tanh factors (signed)
            #pragma unroll
            for (int j = 0; j < DVc; j++) {
                float2 tt = tot2[ip[c][j] & 0xFFFF];
                float2 v  = f2sub(tt, c2vr[c][j]);
                float2 hv = f2mul(v, half2c);
                t[j] = make_float2(ftanh(hv.x), ftanh(hv.y));
            }
            // full product incl. parity factor
            float2 R = t5[c];
            #pragma unroll
            for (int j = 0; j < DVc; j++) R = f2mul(R, t[j]);
            // syndrome: check satisfied iff sign-product of all v2c > 0
            pred &= (R.x > 0.0f) & (R.y > 0.0f);
            // per-edge: dv = ln2*(lg2|t+R| - lg2|t-R|) = 2*atanh(R/t), sign automatic
            #pragma unroll
            for (int j = 0; j < DVc; j++) {
                float2 a2 = f2add(t[j], R);
                float2 b2 = f2sub(t[j], R);
                float aA = fmaxf(fabsf(a2.x), TINYF);
                float aB = fmaxf(fabsf(a2.y), TINYF);
                float bA = fmaxf(fabsf(b2.x), fmaxf(SATR * aA, TINYF));
                float bB = fmaxf(fabsf(b2.y), fmaxf(SATR * aB, TINYF));
                float2 lgd = make_float2(__log2f(aA) - __log2f(bA),
                                         __log2f(aB) - __log2f(bB));
                float2 msg = f2mul(lgd, ln2_2);
                c2vr[c][j] = msg;
                c2v2[ip[c][j] >> 16] = msg;
            }
        }
        // doubles as the CN->VN barrier
        int stable = __syncthreads_and(pred);

        // VN: contiguous packed segment sums
        #pragma unroll
        for (int c = 0; c < CPT; c++) {
            float2 acc = llr_r2[c];
            int o = voff[c], d = vdeg[c];
            for (int k = 0; k < d; k++) acc = f2add(acc, c2v2[o + k]);
            tot2[tid + c * Tthr] = acc;
        }
        // exit when syndrome satisfied 2 consecutive iterations: messages are at a
        // reinforcing fixed point; tot signs == 20-iter signs. (uniform across block)
        if (stable && prevStable) break;
        prevStable = stable;
        __syncthreads();
    }
    __syncthreads();

    // ---- outputs: [bits, bits_rx] each [B,K] float; b1 = b0+1 ----
    for (int k = tid; k < Kc; k += Tthr) {
        int pk = cwp[k];
        float2 t = tot2[k];
        out[b0 * Kc + k]                = (float)(pk & 1);
        out[b0 * Kc + Kc + k]           = (float)((pk >> 8) & 1);
        out[Bn * Kc + b0 * Kc + k]      = (t.x < 0.0f) ? 1.0f : 0.0f;
        out[Bn * Kc + b0 * Kc + Kc + k] = (t.y < 0.0f) ? 1.0f : 0.0f;
    }
}

extern "C" void kernel_launch(void* const* d_in, const int* in_sizes, int n_in,
                              void* d_out, int out_size)
{
    const int*   bits  = (const int*)  d_in[0];
    const int*   a_idx = (const int*)  d_in[1];
    const float* pre   = (const float*)d_in[4];
    const float* pim   = (const float*)d_in[5];
    const float* nre   = (const float*)d_in[6];
    const float* nim   = (const float*)d_in[7];
    const float* ebno  = (const float*)d_in[8];
    float*       out   = (float*)d_out;

    cudaFuncSetAttribute(simplelink_kernel,
                         cudaFuncAttributeMaxDynamicSharedMemorySize, SMEM_BYTES);
    build_transpose_kernel<<<1, 1024>>>(a_idx);
    simplelink_kernel<<<Bn / 2, Tthr, SMEM_BYTES>>>(bits, a_idx, pre, pim, nre, nim, ebno, out);
}